// round 15
// baseline (speedup 1.0000x reference)
#include <cuda_runtime.h>
#include <cuda_fp16.h>
#include <cstdint>

// ----------------------------------------------------------------------------
// Problem constants
// ----------------------------------------------------------------------------
#define NPTS   262144
#define KOFF   27
#define CIN    64
#define COUT   64
#define TILE_M 128
#define NTILES (NPTS / TILE_M)   // 2048
#define NCTA   444               // persistent grid: 3 CTAs/SM x 148 SMs
#define EPSV   1e-5f

// ----------------------------------------------------------------------------
// Device scratch (static allocations only)
// ----------------------------------------------------------------------------
// Features as fp16, 128B per row; extra zero row at index NPTS.
__device__ __half g_feat[(size_t)(NPTS + 1) * 64];
// Weights in mma-fragment-major layout:
//   uint4 index = ((k*4 + wn2)*4 + ks)*32 + lane  (= k*512 + lin)
__device__ uint4  g_wtf[(size_t)KOFF * 512];
__device__ __half g_convh[(size_t)NPTS * COUT];  // conv output (fp16 scratch)
__device__ float  g_stats[128];                  // [0:64) sum [64:128) sumsq

// ----------------------------------------------------------------------------
// Helpers
// ----------------------------------------------------------------------------
__device__ __forceinline__ uint32_t smem_u32(const void* p) {
    uint32_t a;
    asm("{ .reg .u64 t; cvta.to.shared.u64 t, %1; cvt.u32.u64 %0, t; }"
        : "=r"(a) : "l"(p));
    return a;
}

__device__ __forceinline__ void ldsm4(uint32_t* r, uint32_t addr) {
    asm volatile("ldmatrix.sync.aligned.m8n8.x4.shared.b16 {%0,%1,%2,%3}, [%4];"
                 : "=r"(r[0]), "=r"(r[1]), "=r"(r[2]), "=r"(r[3]) : "r"(addr));
}

__device__ __forceinline__ void mma16816(float* c, const uint32_t* a,
                                         uint32_t b0, uint32_t b1) {
    asm volatile(
        "mma.sync.aligned.m16n8k16.row.col.f32.f16.f16.f32 "
        "{%0,%1,%2,%3}, {%4,%5,%6,%7}, {%8,%9}, {%0,%1,%2,%3};"
        : "+f"(c[0]), "+f"(c[1]), "+f"(c[2]), "+f"(c[3])
        : "r"(a[0]), "r"(a[1]), "r"(a[2]), "r"(a[3]), "r"(b0), "r"(b1));
}

__device__ __forceinline__ void cp16(uint32_t smem_dst, const void* gsrc) {
    asm volatile("cp.async.cg.shared.global [%0], [%1], 16;"
                 :: "r"(smem_dst), "l"(gsrc));
}

// ----------------------------------------------------------------------------
// Kernel 1 (fused prep): features -> fp16 table, weights -> fragment-major,
// stats -> 0, pad row -> 0.
// ----------------------------------------------------------------------------
#define FEAT_BLOCKS  4096      // NPTS*8 groups / (256 thr * 2 groups)

__global__ void prep_kernel(const float* __restrict__ feat,
                            const float* __restrict__ w) {
    const int b = blockIdx.x;
    if (b < FEAT_BLOCKS) {
        const int base = b * 512 + threadIdx.x;
        float4 v[2][2];
        #pragma unroll
        for (int j = 0; j < 2; j++) {               // 4 independent LDG.128
            int g = base + j * 256;
            v[j][0] = ((const float4*)feat)[g * 2];
            v[j][1] = ((const float4*)feat)[g * 2 + 1];
        }
        #pragma unroll
        for (int j = 0; j < 2; j++) {
            int g = base + j * 256;
            uint4 o;
            ((__half2*)&o)[0] = __floats2half2_rn(v[j][0].x, v[j][0].y);
            ((__half2*)&o)[1] = __floats2half2_rn(v[j][0].z, v[j][0].w);
            ((__half2*)&o)[2] = __floats2half2_rn(v[j][1].x, v[j][1].y);
            ((__half2*)&o)[3] = __floats2half2_rn(v[j][1].z, v[j][1].w);
            *(uint4*)(g_feat + (size_t)g * 8) = o;
        }
    } else if (b < FEAT_BLOCKS + KOFF) {
        const int k = b - FEAT_BLOCKS;
        const float* wk = w + (size_t)k * CIN * COUT;   // wk[ci*64 + co]
        #pragma unroll
        for (int j = 0; j < 2; j++) {
            int lin = threadIdx.x + j * 256;            // 0..511
            int wn2 = lin >> 7;
            int ks  = (lin >> 5) & 3;
            int L   = lin & 31;
            int co0 = wn2 * 16 + (L >> 2);
            int ci0 = ks * 16 + (L & 3) * 2;
            uint4 o;
            ((__half2*)&o)[0] = __floats2half2_rn(wk[ci0 * 64 + co0],
                                                  wk[(ci0 + 1) * 64 + co0]);
            ((__half2*)&o)[1] = __floats2half2_rn(wk[(ci0 + 8) * 64 + co0],
                                                  wk[(ci0 + 9) * 64 + co0]);
            ((__half2*)&o)[2] = __floats2half2_rn(wk[ci0 * 64 + co0 + 8],
                                                  wk[(ci0 + 1) * 64 + co0 + 8]);
            ((__half2*)&o)[3] = __floats2half2_rn(wk[(ci0 + 8) * 64 + co0 + 8],
                                                  wk[(ci0 + 9) * 64 + co0 + 8]);
            g_wtf[(size_t)k * 512 + lin] = o;
        }
    } else {
        if (threadIdx.x < 128) g_stats[threadIdx.x] = 0.f;
        if (threadIdx.x < 8) {                      // zero the pad row (128B)
            uint4 z = make_uint4(0u, 0u, 0u, 0u);
            *(uint4*)(g_feat + (size_t)NPTS * 64 + threadIdx.x * 8) = z;
        }
    }
}

// ----------------------------------------------------------------------------
// Kernel 2: PERSISTENT conv.  444 CTAs x 256 threads, each processes tiles
// tile = bid, bid+444, ...  The 4-stage A pipeline runs continuously across
// tile boundaries (weights are tile-invariant; W fragments double-buffered
// straight through).  Per-tile epilogue overlaps the next tile's fills.
// SMEM: 4 x 16KB A stages + 512B sred (stats accumulators).
// ----------------------------------------------------------------------------
#define STAGE    16384
#define SRED_OFF (4 * STAGE)
#define CONV_SMEM (4 * STAGE + 512)

__device__ __forceinline__ void fill_stage(uint32_t buf, int g, int tid) {
    const int row  = tid >> 1;
    const int half = tid & 1;
    const uint32_t key = (uint32_t)(row & 7);
    const int4* fr = (const int4*)g_feat + (size_t)g * 8 + half * 4;
    #pragma unroll
    for (int q = 0; q < 4; q++) {
        uint32_t qq = (uint32_t)(half * 4 + q);
        cp16(buf + (uint32_t)row * 128 + ((qq ^ key) << 4), fr + q);
    }
    asm volatile("cp.async.commit_group;");
}

__global__ void __launch_bounds__(256, 3) conv_kernel(const int* __restrict__ nbr) {
    extern __shared__ char smem[];
    const uint32_t sb  = smem_u32(smem);
    const int tid  = threadIdx.x;
    const int wid  = tid >> 5;
    const int lane = tid & 31;
    const int wm   = wid >> 1;          // 0..3 -> m base wm*32
    const int wn   = wid & 1;           // n base wn*32
    const int bid  = blockIdx.x;

    float* sred = (float*)(smem + SRED_OFF);
    if (tid < 128) sred[tid] = 0.f;     // visible by first per-iter barrier

    float c[2][2][2][4];
    #pragma unroll
    for (int a = 0; a < 2; a++)
        #pragma unroll
        for (int b = 0; b < 2; b++)
            #pragma unroll
            for (int d = 0; d < 2; d++)
                #pragma unroll
                for (int j = 0; j < 4; j++) c[a][b][d][j] = 0.f;

    const int ntiles = (NTILES - bid + NCTA - 1) / NCTA;
    const int total  = ntiles * KOFF;

    // ---- fill-side state ----
    const int* fidx = nbr + bid * TILE_M + (tid >> 1);
    int fk = 0;
    #pragma unroll
    for (int p = 0; p < 3; p++) {       // prologue: fills for j = 0,1,2
        int g = __ldg(fidx + (size_t)fk * NPTS);
        fill_stage(sb + p * STAGE, g, tid);
        if (++fk == KOFF) { fk = 0; fidx += NCTA * TILE_M; }
    }
    int g_next = __ldg(fidx + (size_t)fk * NPTS);   // for j = 3

    // W fragment base for this warp; double buffer primed with k=0, ks=0
    const uint4* wf = g_wtf + (size_t)(wn * 2) * 128 + lane;
    uint4 wb[2][2];
    wb[0][0] = __ldg(wf);
    wb[0][1] = __ldg(wf + 128);

    // ldmatrix invariants (A side)
    const uint32_t arow  = (uint32_t)(wm * 32 + (lane & 15));
    const uint32_t aswz  = (uint32_t)((lane & 15) & 7);
    const uint32_t ahalf = (uint32_t)(lane >> 4);

    // ---- consume-side state ----
    int    ck   = 0;                    // k within current tile
    size_t crow = (size_t)bid * TILE_M; // row0 of current tile

    for (int j = 0; j < total; j++) {
        if (j < total - 2)       asm volatile("cp.async.wait_group 2;");
        else if (j == total - 2) asm volatile("cp.async.wait_group 1;");
        else                     asm volatile("cp.async.wait_group 0;");
        __syncthreads();

        if (j + 3 < total) {
            fill_stage(sb + (uint32_t)((j + 3) & 3) * STAGE, g_next, tid);
            if (++fk == KOFF) { fk = 0; fidx += NCTA * TILE_M; }
            if (j + 4 < total) g_next = __ldg(fidx + (size_t)fk * NPTS);
        }

        const uint32_t A0 = sb + (uint32_t)(j & 3) * STAGE;
        const int knext = (ck + 1 == KOFF) ? 0 : ck + 1;

        #pragma unroll
        for (int ks = 0; ks < 4; ks++) {
            const int cb_ = ks & 1, nb_ = (ks + 1) & 1;
            // prefetch next ks (or next iteration's ks=0; weights tile-invariant)
            {
                const uint4* p = (ks < 3)
                    ? wf + (size_t)ck * 512 + (ks + 1) * 32
                    : wf + (size_t)knext * 512;
                wb[nb_][0] = __ldg(p);
                wb[nb_][1] = __ldg(p + 128);
            }

            const uint32_t aoff = (((uint32_t)(2 * ks) + ahalf) ^ aswz) << 4;
            uint32_t ah[2][4];
            #pragma unroll
            for (int mt = 0; mt < 2; mt++)
                ldsm4(ah[mt], A0 + (arow + mt * 16) * 128 + aoff);

            #pragma unroll
            for (int nc = 0; nc < 2; nc++) {
                const uint32_t b0 = wb[cb_][nc].x, b1 = wb[cb_][nc].y;
                const uint32_t b2 = wb[cb_][nc].z, b3 = wb[cb_][nc].w;
                #pragma unroll
                for (int mt = 0; mt < 2; mt++) {
                    mma16816(c[mt][nc][0], ah[mt], b0, b1);
                    mma16816(c[mt][nc][1], ah[mt], b2, b3);
                }
            }
        }

        if (++ck == KOFF) {
            // ---- per-tile epilogue (overlaps next tile's in-flight fills) ----
            ck = 0;
            const int r0 = (int)crow + wm * 32 + (lane >> 2);
            const int cb2 = wn * 32 + (lane & 3) * 2;
            #pragma unroll
            for (int mt = 0; mt < 2; mt++) {
                const int r = r0 + mt * 16;
                #pragma unroll
                for (int nc = 0; nc < 2; nc++) {
                    #pragma unroll
                    for (int n8 = 0; n8 < 2; n8++) {
                        const int col = cb2 + nc * 16 + n8 * 8;
                        float v0 = c[mt][nc][n8][0], v1 = c[mt][nc][n8][1];
                        float v2 = c[mt][nc][n8][2], v3 = c[mt][nc][n8][3];
                        *(__half2*)(g_convh + (size_t)r * COUT + col) =
                            __floats2half2_rn(v0, v1);
                        *(__half2*)(g_convh + (size_t)(r + 8) * COUT + col) =
                            __floats2half2_rn(v2, v3);
                        // stats partials -> warp shuffle -> smem atomics
                        float s0 = v0 + v2, q0 = v0 * v0 + v2 * v2;
                        float s1 = v1 + v3, q1 = v1 * v1 + v3 * v3;
                        #pragma unroll
                        for (int sh = 4; sh <= 16; sh <<= 1) {
                            s0 += __shfl_xor_sync(0xFFFFFFFFu, s0, sh);
                            q0 += __shfl_xor_sync(0xFFFFFFFFu, q0, sh);
                            s1 += __shfl_xor_sync(0xFFFFFFFFu, s1, sh);
                            q1 += __shfl_xor_sync(0xFFFFFFFFu, q1, sh);
                        }
                        if ((lane >> 2) == 0) {
                            atomicAdd(&sred[col],          s0);
                            atomicAdd(&sred[64 + col],     q0);
                            atomicAdd(&sred[col + 1],      s1);
                            atomicAdd(&sred[64 + col + 1], q1);
                        }
                        c[mt][nc][n8][0] = 0.f; c[mt][nc][n8][1] = 0.f;
                        c[mt][nc][n8][2] = 0.f; c[mt][nc][n8][3] = 0.f;
                    }
                }
            }
            crow += (size_t)NCTA * TILE_M;
        }
    }

    // ---- final stats flush ----
    __syncthreads();
    if (tid < 128) atomicAdd(&g_stats[tid], sred[tid]);
}

// ----------------------------------------------------------------------------
// Kernel 3: apply BN + ReLU, 4 float4 outputs per thread (ILP=4), exact grid.
// ----------------------------------------------------------------------------
__global__ void apply_kernel(const float* __restrict__ gamma,
                             const float* __restrict__ beta,
                             float* __restrict__ out) {
    __shared__ float ssc[64], ssh[64];
    const int t = threadIdx.x;
    if (t < 64) {
        float mean = g_stats[t] * (1.f / (float)NPTS);
        float var  = g_stats[64 + t] * (1.f / (float)NPTS) - mean * mean;
        float sc   = gamma[t] * rsqrtf(var + EPSV);
        ssc[t] = sc;
        ssh[t] = beta[t] - mean * sc;
    }
    __syncthreads();

    const int base = blockIdx.x * 1024 + t;      // float4 output index
    uint2 hv[4];
    #pragma unroll
    for (int j = 0; j < 4; j++)                  // 4 independent 8B loads
        hv[j] = ((const uint2*)g_convh)[base + j * 256];
    #pragma unroll
    for (int j = 0; j < 4; j++) {
        const int i = base + j * 256;
        float2 f0 = __half22float2(*(__half2*)&hv[j].x);
        float2 f1 = __half22float2(*(__half2*)&hv[j].y);
        const int c0 = (i & 15) * 4;
        float4 r;
        r.x = fmaxf(fmaf(f0.x, ssc[c0],     ssh[c0]),     0.f);
        r.y = fmaxf(fmaf(f0.y, ssc[c0 + 1], ssh[c0 + 1]), 0.f);
        r.z = fmaxf(fmaf(f1.x, ssc[c0 + 2], ssh[c0 + 2]), 0.f);
        r.w = fmaxf(fmaf(f1.y, ssc[c0 + 3], ssh[c0 + 3]), 0.f);
        ((float4*)out)[i] = r;
    }
}

// ----------------------------------------------------------------------------
// Launch
// ----------------------------------------------------------------------------
extern "C" void kernel_launch(void* const* d_in, const int* in_sizes, int n_in,
                              void* d_out, int out_size) {
    const float* feat  = (const float*)d_in[0];
    const int*   nbr   = (const int*)d_in[1];
    const float* w     = (const float*)d_in[2];
    const float* gamma = (const float*)d_in[3];
    const float* beta  = (const float*)d_in[4];
    float*       out   = (float*)d_out;
    (void)in_sizes; (void)n_in; (void)out_size;

    cudaFuncSetAttribute(conv_kernel,
                         cudaFuncAttributeMaxDynamicSharedMemorySize, CONV_SMEM);

    prep_kernel<<<FEAT_BLOCKS + KOFF + 1, 256>>>(feat, w);
    conv_kernel<<<NCTA, 256, CONV_SMEM>>>(nbr);
    apply_kernel<<<(NPTS * COUT / 4) / 1024, 256>>>(gamma, beta, out);
}

// round 16
// speedup vs baseline: 1.1501x; 1.1501x over previous
#include <cuda_runtime.h>
#include <cuda_fp16.h>
#include <cstdint>

// ----------------------------------------------------------------------------
// Problem constants
// ----------------------------------------------------------------------------
#define NPTS   262144
#define KOFF   27
#define CIN    64
#define COUT   64
#define TILE_M 128
#define NTILES (NPTS / TILE_M)   // 2048
#define EPSV   1e-5f

// ----------------------------------------------------------------------------
// Device scratch (static allocations only)
// ----------------------------------------------------------------------------
// Features as fp16, 128B per row; extra zero row at index NPTS.
__device__ __half g_feat[(size_t)(NPTS + 1) * 64];
// Weights in mma-fragment-major layout:
//   uint4 index = ((k*4 + wn2)*4 + ks)*32 + lane  (= k*512 + lin)
//   lane's uint4 = { B[co0][ci0,ci0+1], B[co0][ci0+8,+9],
//                    B[co0+8][ci0,+1],  B[co0+8][ci0+8,+9] }  as half2s
//   with co0 = wn2*16 + lane/4, ci0 = ks*16 + (lane%4)*2   (B[co][ci] = W^T)
__device__ uint4  g_wtf[(size_t)KOFF * 512];
__device__ __half g_convh[(size_t)NPTS * COUT];  // conv output (fp16 scratch)
__device__ float  g_stats[128];                  // [0:64) sum [64:128) sumsq

// ----------------------------------------------------------------------------
// Helpers
// ----------------------------------------------------------------------------
__device__ __forceinline__ uint32_t smem_u32(const void* p) {
    uint32_t a;
    asm("{ .reg .u64 t; cvta.to.shared.u64 t, %1; cvt.u32.u64 %0, t; }"
        : "=r"(a) : "l"(p));
    return a;
}

__device__ __forceinline__ void ldsm4(uint32_t* r, uint32_t addr) {
    asm volatile("ldmatrix.sync.aligned.m8n8.x4.shared.b16 {%0,%1,%2,%3}, [%4];"
                 : "=r"(r[0]), "=r"(r[1]), "=r"(r[2]), "=r"(r[3]) : "r"(addr));
}

__device__ __forceinline__ void mma16816(float* c, const uint32_t* a,
                                         uint32_t b0, uint32_t b1) {
    asm volatile(
        "mma.sync.aligned.m16n8k16.row.col.f32.f16.f16.f32 "
        "{%0,%1,%2,%3}, {%4,%5,%6,%7}, {%8,%9}, {%0,%1,%2,%3};"
        : "+f"(c[0]), "+f"(c[1]), "+f"(c[2]), "+f"(c[3])
        : "r"(a[0]), "r"(a[1]), "r"(a[2]), "r"(a[3]), "r"(b0), "r"(b1));
}

__device__ __forceinline__ void cp16(uint32_t smem_dst, const void* gsrc) {
    asm volatile("cp.async.cg.shared.global [%0], [%1], 16;"
                 :: "r"(smem_dst), "l"(gsrc));
}

// ----------------------------------------------------------------------------
// Kernel 1 (fused prep):
//  - features -> fp16 table (exact grid, 2 groups/thread)
//  - weights -> fragment-major g_wtf
//  - stats -> 0, pad row -> 0
// ----------------------------------------------------------------------------
#define FEAT_BLOCKS  4096      // NPTS*8 groups / (256 thr * 2 groups)

__global__ void prep_kernel(const float* __restrict__ feat,
                            const float* __restrict__ w) {
    const int b = blockIdx.x;
    if (b < FEAT_BLOCKS) {
        const int base = b * 512 + threadIdx.x;
        float4 v[2][2];
        #pragma unroll
        for (int j = 0; j < 2; j++) {               // 4 independent LDG.128
            int g = base + j * 256;
            v[j][0] = ((const float4*)feat)[g * 2];
            v[j][1] = ((const float4*)feat)[g * 2 + 1];
        }
        #pragma unroll
        for (int j = 0; j < 2; j++) {
            int g = base + j * 256;
            uint4 o;
            ((__half2*)&o)[0] = __floats2half2_rn(v[j][0].x, v[j][0].y);
            ((__half2*)&o)[1] = __floats2half2_rn(v[j][0].z, v[j][0].w);
            ((__half2*)&o)[2] = __floats2half2_rn(v[j][1].x, v[j][1].y);
            ((__half2*)&o)[3] = __floats2half2_rn(v[j][1].z, v[j][1].w);
            *(uint4*)(g_feat + (size_t)g * 8) = o;
        }
    } else if (b < FEAT_BLOCKS + KOFF) {
        const int k = b - FEAT_BLOCKS;
        const float* wk = w + (size_t)k * CIN * COUT;   // wk[ci*64 + co]
        #pragma unroll
        for (int j = 0; j < 2; j++) {
            int lin = threadIdx.x + j * 256;            // 0..511
            int wn2 = lin >> 7;                         // 0..3
            int ks  = (lin >> 5) & 3;                   // 0..3
            int L   = lin & 31;                         // lane
            int co0 = wn2 * 16 + (L >> 2);
            int ci0 = ks * 16 + (L & 3) * 2;
            uint4 o;
            ((__half2*)&o)[0] = __floats2half2_rn(wk[ci0 * 64 + co0],
                                                  wk[(ci0 + 1) * 64 + co0]);
            ((__half2*)&o)[1] = __floats2half2_rn(wk[(ci0 + 8) * 64 + co0],
                                                  wk[(ci0 + 9) * 64 + co0]);
            ((__half2*)&o)[2] = __floats2half2_rn(wk[ci0 * 64 + co0 + 8],
                                                  wk[(ci0 + 1) * 64 + co0 + 8]);
            ((__half2*)&o)[3] = __floats2half2_rn(wk[(ci0 + 8) * 64 + co0 + 8],
                                                  wk[(ci0 + 9) * 64 + co0 + 8]);
            g_wtf[(size_t)k * 512 + lin] = o;
        }
    } else {
        if (threadIdx.x < 128) g_stats[threadIdx.x] = 0.f;
        if (threadIdx.x < 8) {                      // zero the pad row (128B)
            uint4 z = make_uint4(0u, 0u, 0u, 0u);
            *(uint4*)(g_feat + (size_t)NPTS * 64 + threadIdx.x * 8) = z;
        }
    }
}

// ----------------------------------------------------------------------------
// Kernel 2: 4-stage cp.async pipeline (A only), 3 CTAs/SM; W via direct
// fragment LDG.128 from L2, double-buffered across ks.
// 2048 CTAs x 256 threads (8 warps, warp grid 4M x 2N, 32x32 per warp).
// Stage (16KB): A[128][128B], XOR-quad swizzle.
// Iter k: wait fill(k) -> barrier (retires MMA(k-1)) -> issue fill(k+3)
// (targets MMA(k-1)'s buffer: safe) -> MMA(k).
// ----------------------------------------------------------------------------
#define STAGE    16384
#define NSTAGE   4
#define CONV_SMEM (NSTAGE * STAGE)

__device__ __forceinline__ void fill_stage(uint32_t buf, int g, int tid) {
    // A: thread covers row tid>>1, half tid&1 (4 x int4 = 64B)
    const int row  = tid >> 1;
    const int half = tid & 1;
    const uint32_t key = (uint32_t)(row & 7);
    const int4* fr = (const int4*)g_feat + (size_t)g * 8 + half * 4;
    #pragma unroll
    for (int q = 0; q < 4; q++) {
        uint32_t qq = (uint32_t)(half * 4 + q);
        cp16(buf + (uint32_t)row * 128 + ((qq ^ key) << 4), fr + q);
    }
    asm volatile("cp.async.commit_group;");
}

__global__ void __launch_bounds__(256, 3) conv_kernel(const int* __restrict__ nbr) {
    extern __shared__ char smem[];
    const uint32_t sb  = smem_u32(smem);
    const int tid  = threadIdx.x;
    const int wid  = tid >> 5;
    const int lane = tid & 31;
    const int wm   = wid >> 1;          // 0..3 -> m base wm*32
    const int wn   = wid & 1;           // n base wn*32
    const int row0 = blockIdx.x * TILE_M;

    float c[2][2][2][4];                // [mt][nc][n8][frag]
    #pragma unroll
    for (int a = 0; a < 2; a++)
        #pragma unroll
        for (int b = 0; b < 2; b++)
            #pragma unroll
            for (int d = 0; d < 2; d++)
                #pragma unroll
                for (int j = 0; j < 4; j++) c[a][b][d][j] = 0.f;

    const int* idxp = nbr + row0 + (tid >> 1);  // this thread's gather row

    // W fragment base for this warp: [k][wn2=wn*2+nc][ks][lane]
    const uint4* wf = g_wtf + (size_t)(wn * 2) * 128 + lane;
    // offsets: +nc*128, +ks*32, +k*512

    // --- prologue: fill stages for k = 0,1,2; preload W(k=0, ks=0) ---
    {
        int g0 = __ldg(idxp);
        int g1 = __ldg(idxp + NPTS);
        int g2 = __ldg(idxp + 2 * NPTS);
        fill_stage(sb,             g0, tid);
        fill_stage(sb + STAGE,     g1, tid);
        fill_stage(sb + 2 * STAGE, g2, tid);
    }
    int g_next = __ldg(idxp + (size_t)3 * NPTS);   // idx for k=3

    uint4 wb[2][2];                     // [buf][nc] W fragments
    wb[0][0] = __ldg(wf);
    wb[0][1] = __ldg(wf + 128);

    // ldmatrix invariants (A side)
    const uint32_t arow  = (uint32_t)(wm * 32 + (lane & 15));
    const uint32_t aswz  = (uint32_t)((lane & 15) & 7);
    const uint32_t ahalf = (uint32_t)(lane >> 4);

    for (int k = 0; k < KOFF; k++) {
        // fill(k) done (per-thread), then barrier: visibility + retire MMA(k-1)
        if (k < KOFF - 2)       asm volatile("cp.async.wait_group 2;");
        else if (k == KOFF - 2) asm volatile("cp.async.wait_group 1;");
        else                    asm volatile("cp.async.wait_group 0;");
        __syncthreads();

        if (k + 3 < KOFF) {
            fill_stage(sb + (uint32_t)((k + 3) & 3) * STAGE, g_next, tid);
            if (k + 4 < KOFF) g_next = __ldg(idxp + (size_t)(k + 4) * NPTS);
        }

        const uint32_t A0 = sb + (uint32_t)(k & 3) * STAGE;

        #pragma unroll
        for (int ks = 0; ks < 4; ks++) {
            const int cb_ = ks & 1, nb_ = (ks + 1) & 1;
            // prefetch next ks (or next k's ks=0) while mma runs
            if (ks < 3) {
                const uint4* p = wf + (size_t)k * 512 + (ks + 1) * 32;
                wb[nb_][0] = __ldg(p);
                wb[nb_][1] = __ldg(p + 128);
            } else if (k + 1 < KOFF) {
                const uint4* p = wf + (size_t)(k + 1) * 512;
                wb[nb_][0] = __ldg(p);
                wb[nb_][1] = __ldg(p + 128);
            }

            const uint32_t aoff = (((uint32_t)(2 * ks) + ahalf) ^ aswz) << 4;
            uint32_t ah[2][4];
            #pragma unroll
            for (int mt = 0; mt < 2; mt++)
                ldsm4(ah[mt], A0 + (arow + mt * 16) * 128 + aoff);

            #pragma unroll
            for (int nc = 0; nc < 2; nc++) {
                const uint32_t b0 = wb[cb_][nc].x, b1 = wb[cb_][nc].y;
                const uint32_t b2 = wb[cb_][nc].z, b3 = wb[cb_][nc].w;
                #pragma unroll
                for (int mt = 0; mt < 2; mt++) {
                    mma16816(c[mt][nc][0], ah[mt], b0, b1);
                    mma16816(c[mt][nc][1], ah[mt], b2, b3);
                }
            }
        }
        // no trailing barrier: next iteration's barrier retires these MMAs
    }

    // --- epilogue: write 128x64 fp16 tile + per-channel partial stats ---
    const int r0 = row0 + wm * 32 + (lane >> 2);
    const int cb = wn * 32 + (lane & 3) * 2;
    float ls[2][2][2], lq[2][2][2];     // [nc][n8][j] sums / sumsqs
    #pragma unroll
    for (int nc = 0; nc < 2; nc++)
        #pragma unroll
        for (int n8 = 0; n8 < 2; n8++)
            #pragma unroll
            for (int j = 0; j < 2; j++) { ls[nc][n8][j] = 0.f; lq[nc][n8][j] = 0.f; }

    #pragma unroll
    for (int mt = 0; mt < 2; mt++) {
        const int r = r0 + mt * 16;
        #pragma unroll
        for (int nc = 0; nc < 2; nc++) {
            #pragma unroll
            for (int n8 = 0; n8 < 2; n8++) {
                const int col = cb + nc * 16 + n8 * 8;
                float v0 = c[mt][nc][n8][0], v1 = c[mt][nc][n8][1];
                float v2 = c[mt][nc][n8][2], v3 = c[mt][nc][n8][3];
                *(__half2*)(g_convh + (size_t)r * COUT + col) =
                    __floats2half2_rn(v0, v1);
                *(__half2*)(g_convh + (size_t)(r + 8) * COUT + col) =
                    __floats2half2_rn(v2, v3);
                ls[nc][n8][0] += v0 + v2;  lq[nc][n8][0] += v0 * v0 + v2 * v2;
                ls[nc][n8][1] += v1 + v3;  lq[nc][n8][1] += v1 * v1 + v3 * v3;
            }
        }
    }

    // reduce across the 8 lanes sharing (lane & 3)
    #pragma unroll
    for (int nc = 0; nc < 2; nc++)
        #pragma unroll
        for (int n8 = 0; n8 < 2; n8++)
            #pragma unroll
            for (int j = 0; j < 2; j++) {
                float s = ls[nc][n8][j], q = lq[nc][n8][j];
                #pragma unroll
                for (int sh = 4; sh <= 16; sh <<= 1) {
                    s += __shfl_xor_sync(0xFFFFFFFFu, s, sh);
                    q += __shfl_xor_sync(0xFFFFFFFFu, q, sh);
                }
                ls[nc][n8][j] = s; lq[nc][n8][j] = q;
            }

    float* sred = (float*)smem;         // reuse stage 0 (all MMA reads done)
    __syncthreads();
    if (tid < 128) sred[tid] = 0.f;
    __syncthreads();
    if ((lane >> 2) == 0) {             // lanes 0..3 per warp
        #pragma unroll
        for (int nc = 0; nc < 2; nc++)
            #pragma unroll
            for (int n8 = 0; n8 < 2; n8++)
                #pragma unroll
                for (int j = 0; j < 2; j++) {
                    const int col = cb + nc * 16 + n8 * 8 + j;
                    atomicAdd(&sred[col],      ls[nc][n8][j]);
                    atomicAdd(&sred[64 + col], lq[nc][n8][j]);
                }
    }
    __syncthreads();
    if (tid < 128) atomicAdd(&g_stats[tid], sred[tid]);
}

// ----------------------------------------------------------------------------
// Kernel 3: apply BN + ReLU, 4 float4 outputs per thread (ILP=4), exact grid.
// Per-block recompute of scale/shift from g_stats.
// ----------------------------------------------------------------------------
__global__ void apply_kernel(const float* __restrict__ gamma,
                             const float* __restrict__ beta,
                             float* __restrict__ out) {
    __shared__ float ssc[64], ssh[64];
    const int t = threadIdx.x;
    if (t < 64) {
        float mean = g_stats[t] * (1.f / (float)NPTS);
        float var  = g_stats[64 + t] * (1.f / (float)NPTS) - mean * mean;
        float sc   = gamma[t] * rsqrtf(var + EPSV);
        ssc[t] = sc;
        ssh[t] = beta[t] - mean * sc;
    }
    __syncthreads();

    const int base = blockIdx.x * 1024 + t;      // float4 output index
    uint2 hv[4];
    #pragma unroll
    for (int j = 0; j < 4; j++)                  // 4 independent 8B loads
        hv[j] = ((const uint2*)g_convh)[base + j * 256];
    #pragma unroll
    for (int j = 0; j < 4; j++) {
        const int i = base + j * 256;
        float2 f0 = __half22float2(*(__half2*)&hv[j].x);
        float2 f1 = __half22float2(*(__half2*)&hv[j].y);
        const int c0 = (i & 15) * 4;
        float4 r;
        r.x = fmaxf(fmaf(f0.x, ssc[c0],     ssh[c0]),     0.f);
        r.y = fmaxf(fmaf(f0.y, ssc[c0 + 1], ssh[c0 + 1]), 0.f);
        r.z = fmaxf(fmaf(f1.x, ssc[c0 + 2], ssh[c0 + 2]), 0.f);
        r.w = fmaxf(fmaf(f1.y, ssc[c0 + 3], ssh[c0 + 3]), 0.f);
        ((float4*)out)[i] = r;
    }
}

// ----------------------------------------------------------------------------
// Launch
// ----------------------------------------------------------------------------
extern "C" void kernel_launch(void* const* d_in, const int* in_sizes, int n_in,
                              void* d_out, int out_size) {
    const float* feat  = (const float*)d_in[0];
    const int*   nbr   = (const int*)d_in[1];
    const float* w     = (const float*)d_in[2];
    const float* gamma = (const float*)d_in[3];
    const float* beta  = (const float*)d_in[4];
    float*       out   = (float*)d_out;
    (void)in_sizes; (void)n_in; (void)out_size;

    cudaFuncSetAttribute(conv_kernel,
                         cudaFuncAttributeMaxDynamicSharedMemorySize, CONV_SMEM);

    prep_kernel<<<FEAT_BLOCKS + KOFF + 1, 256>>>(feat, w);
    conv_kernel<<<NTILES, 256, CONV_SMEM>>>(nbr);
    apply_kernel<<<(NPTS * COUT / 4) / 1024, 256>>>(gamma, beta, out);
}